// round 1
// baseline (speedup 1.0000x reference)
#include <cuda_runtime.h>
#include <cuda_bf16.h>
#include <cstdint>

// Problem constants
#define BSZ   128
#define CDIM  2048
#define HW    196          // 14*14
#define NDESC 32
#define NANS  1845

// Scratch (no allocations allowed)
__device__ float g_att[BSZ * CDIM];      // attended [B, C]
__device__ int   g_cnt[NDESC];           // samples per descriptor
__device__ int   g_list[NDESC * BSZ];    // sample ids per descriptor

// ---------------------------------------------------------------------------
// Kernel A: attended[b,c] = (1/196) * sum_hw mask[b,hw] * feat[b,c,hw]
// grid (32, 128), block 256. Each block: one b, 64 channels (8 warps x 8 iters).
// Rows are 196 floats = 784 bytes = 49 float4 (16B aligned).
// ---------------------------------------------------------------------------
__global__ void attend_kernel(const float* __restrict__ mask,
                              const float* __restrict__ feat) {
    __shared__ float4 smask[49];
    const int b = blockIdx.y;
    const int tid = threadIdx.x;

    const float4* mrow = reinterpret_cast<const float4*>(mask + (size_t)b * HW);
    if (tid < 49) smask[tid] = mrow[tid];
    __syncthreads();

    const int warp = tid >> 5;
    const int lane = tid & 31;

    #pragma unroll
    for (int it = 0; it < 8; ++it) {
        const int c = blockIdx.x * 64 + it * 8 + warp;
        const float4* frow =
            reinterpret_cast<const float4*>(feat + ((size_t)b * CDIM + c) * HW);

        float s = 0.0f;
        {   // float4 index = lane (always < 49)
            float4 f = frow[lane];
            float4 m = smask[lane];
            s += f.x * m.x + f.y * m.y + f.z * m.z + f.w * m.w;
        }
        if (lane < 17) {  // float4 index = lane + 32 (< 49)
            float4 f = frow[lane + 32];
            float4 m = smask[lane + 32];
            s += f.x * m.x + f.y * m.y + f.z * m.z + f.w * m.w;
        }
        // warp reduce
        #pragma unroll
        for (int off = 16; off > 0; off >>= 1)
            s += __shfl_xor_sync(0xffffffffu, s, off);

        if (lane == 0)
            g_att[(size_t)b * CDIM + c] = s * (1.0f / (float)HW);
    }
}

// ---------------------------------------------------------------------------
// Kernel B: bucket samples by descriptor. Single thread (128 elements).
// Handles instance stored as int64 OR int32 (JAX x64-off downcasts silently):
// if int64 little-endian, every odd 32-bit word of the first 64 entries is 0.
// ---------------------------------------------------------------------------
__global__ void group_kernel(const int* __restrict__ inst32) {
    bool is64 = true;
    for (int b = 0; b < 64; ++b) {           // max index 127: safe either way
        if (inst32[2 * b + 1] != 0) { is64 = false; break; }
    }
    for (int d = 0; d < NDESC; ++d) g_cnt[d] = 0;
    for (int b = 0; b < BSZ; ++b) {
        int d = is64 ? inst32[2 * b] : inst32[b];
        g_list[d * BSZ + g_cnt[d]++] = b;
    }
}

// ---------------------------------------------------------------------------
// Kernel C: grouped GEMM.  preds[s,a] = sum_c att[s,c] * W[d,a,c] + bias[d,a]
// grid (ceil(1845/32)=58, 32).  block 256 = 8 warps.
// Each warp owns 4 answers; each thread accumulates 4 answers x 8 samples.
// attended staged in smem in 8x512 tiles; W streamed coalesced (DRAM-bound).
// ---------------------------------------------------------------------------
#define KC 512
#define TSAMP 8

__global__ void __launch_bounds__(256)
gemm_kernel(const float* __restrict__ Wm,
            const float* __restrict__ bias,
            float* __restrict__ out) {
    const int d = blockIdx.y;
    const int count = g_cnt[d];
    if (count == 0) return;

    const int tid  = threadIdx.x;
    const int warp = tid >> 5;
    const int lane = tid & 31;
    const int aw   = blockIdx.x * 32 + warp * 4;   // first of 4 answers for this warp

    __shared__ float s_att[TSAMP][KC];
    __shared__ int   s_b[TSAMP];

    const int nchunks = (count + TSAMP - 1) / TSAMP;

    for (int sc = 0; sc < nchunks; ++sc) {
        if (tid < TSAMP) {
            int si = sc * TSAMP + tid;
            s_b[tid] = (si < count) ? g_list[d * BSZ + si] : -1;
        }

        float acc[4][TSAMP];
        #pragma unroll
        for (int ta = 0; ta < 4; ++ta)
            #pragma unroll
            for (int ts = 0; ts < TSAMP; ++ts) acc[ta][ts] = 0.0f;

        #pragma unroll
        for (int ct = 0; ct < CDIM / KC; ++ct) {
            __syncthreads();   // s_b visible; previous tile consumers done
            // cooperative load of attended tile (zeros for padding samples)
            for (int i = tid; i < TSAMP * KC; i += 256) {
                int ts = i / KC, cc = i % KC;
                int bb = s_b[ts];
                s_att[ts][cc] =
                    (bb >= 0) ? g_att[(size_t)bb * CDIM + ct * KC + cc] : 0.0f;
            }
            __syncthreads();

            const float* Wp = Wm + ((size_t)d * NANS + aw) * CDIM + ct * KC;

            for (int cc = lane; cc < KC; cc += 32) {
                float av[TSAMP];
                #pragma unroll
                for (int ts = 0; ts < TSAMP; ++ts) av[ts] = s_att[ts][cc];
                #pragma unroll
                for (int ta = 0; ta < 4; ++ta) {
                    float w = (aw + ta < NANS) ? Wp[(size_t)ta * CDIM + cc] : 0.0f;
                    #pragma unroll
                    for (int ts = 0; ts < TSAMP; ++ts)
                        acc[ta][ts] += w * av[ts];
                }
            }
        }

        // full butterfly reductions: every lane ends with the lane-sum totals
        #pragma unroll
        for (int ta = 0; ta < 4; ++ta)
            #pragma unroll
            for (int ts = 0; ts < TSAMP; ++ts)
                #pragma unroll
                for (int off = 16; off > 0; off >>= 1)
                    acc[ta][ts] += __shfl_xor_sync(0xffffffffu, acc[ta][ts], off);

        // lane l stores pair (ta = l/8, ts = l%8)
        {
            int ta = lane >> 3;
            int ts = lane & 7;
            int a  = aw + ta;
            int bb = s_b[ts];
            if (a < NANS && bb >= 0)
                out[(size_t)bb * NANS + a] = acc[ta][ts] + bias[(size_t)d * NANS + a];
        }
        __syncthreads();   // protect s_b / s_att before next chunk rewrites
    }
}

// ---------------------------------------------------------------------------
extern "C" void kernel_launch(void* const* d_in, const int* in_sizes, int n_in,
                              void* d_out, int out_size) {
    const float* mask = (const float*)d_in[0];   // [B,1,14,14]
    const float* feat = (const float*)d_in[1];   // [B,C,14,14]
    const int*   inst = (const int*)d_in[2];     // [B] int64 or int32
    const float* Wm   = (const float*)d_in[3];   // [32,1845,2048]
    const float* bias = (const float*)d_in[4];   // [32,1845]
    float* out = (float*)d_out;                  // [B,1845]

    attend_kernel<<<dim3(32, 128), 256>>>(mask, feat);
    group_kernel<<<1, 1>>>(inst);
    gemm_kernel<<<dim3((NANS + 31) / 32, NDESC), 256>>>(Wm, bias, out);
}

// round 2
// speedup vs baseline: 1.3818x; 1.3818x over previous
#include <cuda_runtime.h>
#include <cuda_bf16.h>
#include <cstdint>

// Problem constants
#define BSZ   128
#define CDIM  2048
#define HW    196          // 14*14
#define NDESC 32
#define NANS  1845

// Scratch (no allocations allowed)
__device__ float g_att[BSZ * CDIM];      // attended [B, C]

// ---------------------------------------------------------------------------
// Kernel A: attended[b,c] = (1/196) * sum_hw mask[b,hw] * feat[b,c,hw]
// grid (32, 128), block 256. Each block: one b, 64 channels.
// Each warp processes channels in pairs -> 4 independent LDG.128 in flight.
// Rows are 196 floats = 784 bytes = 49 float4 (16B aligned).
// ---------------------------------------------------------------------------
__global__ void __launch_bounds__(256)
attend_kernel(const float* __restrict__ mask,
              const float* __restrict__ feat) {
    __shared__ float4 smask[49];
    const int b   = blockIdx.y;
    const int tid = threadIdx.x;

    const float4* mrow = reinterpret_cast<const float4*>(mask + (size_t)b * HW);
    if (tid < 49) smask[tid] = mrow[tid];
    __syncthreads();

    const int warp = tid >> 5;
    const int lane = tid & 31;

    #pragma unroll
    for (int it = 0; it < 4; ++it) {
        // two channels per iteration per warp
        const int c0 = blockIdx.x * 64 + it * 16 + warp * 2;
        const float4* fr0 =
            reinterpret_cast<const float4*>(feat + ((size_t)b * CDIM + c0) * HW);
        const float4* fr1 =
            reinterpret_cast<const float4*>(feat + ((size_t)b * CDIM + c0 + 1) * HW);

        // issue all 4 loads up front (2 per row)
        float4 f0a = fr0[lane];
        float4 f1a = fr1[lane];
        float4 f0b, f1b;
        if (lane < 17) { f0b = fr0[lane + 32]; f1b = fr1[lane + 32]; }

        float4 ma = smask[lane];
        float s0 = f0a.x * ma.x + f0a.y * ma.y + f0a.z * ma.z + f0a.w * ma.w;
        float s1 = f1a.x * ma.x + f1a.y * ma.y + f1a.z * ma.z + f1a.w * ma.w;
        if (lane < 17) {
            float4 mb = smask[lane + 32];
            s0 += f0b.x * mb.x + f0b.y * mb.y + f0b.z * mb.z + f0b.w * mb.w;
            s1 += f1b.x * mb.x + f1b.y * mb.y + f1b.z * mb.z + f1b.w * mb.w;
        }
        #pragma unroll
        for (int off = 16; off > 0; off >>= 1) {
            s0 += __shfl_xor_sync(0xffffffffu, s0, off);
            s1 += __shfl_xor_sync(0xffffffffu, s1, off);
        }
        if (lane == 0) {
            g_att[(size_t)b * CDIM + c0]     = s0 * (1.0f / (float)HW);
            g_att[(size_t)b * CDIM + c0 + 1] = s1 * (1.0f / (float)HW);
        }
    }
}

// ---------------------------------------------------------------------------
// Kernel B: grouped GEMM with fused per-block grouping.
// preds[s,a] = sum_c att[s,c] * W[d,a,c] + bias[d,a]
// grid (ceil(1845/32)=58, 32).  block 256 = 8 warps.
// Each warp owns 4 answers; each thread accumulates 4 answers x 8 samples.
// attended staged in smem in 8x1024 float chunks (32KB); W streamed via
// float4 coalesced loads (DRAM-bound by design).
// ---------------------------------------------------------------------------
#define KC     1024
#define KC4    (KC / 4)       // 256 float4 per chunk row
#define TSAMP  8

__global__ void __launch_bounds__(256)
gemm_kernel(const int* __restrict__ inst32,
            const float* __restrict__ Wm,
            const float* __restrict__ bias,
            float* __restrict__ out) {
    const int d    = blockIdx.y;
    const int tid  = threadIdx.x;
    const int warp = tid >> 5;
    const int lane = tid & 31;

    __shared__ float4 s_att[TSAMP][KC4];   // 32 KB
    __shared__ int    s_inst[BSZ];
    __shared__ int    s_list[BSZ];
    __shared__ int    s_meta[2];           // [0]=count, [1]=is64 flag accumulator

    // ---- fused grouping (parallel loads, tiny smem scan) ----
    if (tid == 0) s_meta[1] = 0;
    __syncthreads();
    if (tid < 64) {
        // if instance is int64 (little-endian), all odd words of first 64 are 0
        if (inst32[2 * tid + 1] != 0) atomicOr(&s_meta[1], 1);
    }
    __syncthreads();
    const bool is64 = (s_meta[1] == 0);
    if (tid < BSZ) s_inst[tid] = is64 ? inst32[2 * tid] : inst32[tid];
    __syncthreads();
    if (tid == 0) {
        int cnt = 0;
        for (int b = 0; b < BSZ; ++b)
            if (s_inst[b] == d) s_list[cnt++] = b;
        s_meta[0] = cnt;
    }
    __syncthreads();
    const int count = s_meta[0];
    if (count == 0) return;   // uniform across block

    // answer rows for this warp (clamped; stores guarded)
    const int aw = blockIdx.x * 32 + warp * 4;
    const float4* __restrict__ W4 = reinterpret_cast<const float4*>(Wm);
    size_t wrow[4];
    #pragma unroll
    for (int ta = 0; ta < 4; ++ta) {
        int a = aw + ta; if (a >= NANS) a = NANS - 1;
        wrow[ta] = ((size_t)d * NANS + a) * (CDIM / 4);
    }
    const float4* __restrict__ gatt4 = reinterpret_cast<const float4*>(g_att);

    __shared__ int s_b[TSAMP];
    const int nchunks = (count + TSAMP - 1) / TSAMP;

    for (int sc = 0; sc < nchunks; ++sc) {
        if (tid < TSAMP) {
            int si = sc * TSAMP + tid;
            s_b[tid] = (si < count) ? s_list[si] : -1;
        }

        float acc[4][TSAMP];
        #pragma unroll
        for (int ta = 0; ta < 4; ++ta)
            #pragma unroll
            for (int ts = 0; ts < TSAMP; ++ts) acc[ta][ts] = 0.0f;

        #pragma unroll
        for (int ct = 0; ct < CDIM / KC; ++ct) {
            __syncthreads();   // s_b visible; previous tile consumers done
            // cooperative vector load of attended tile (zeros for padding)
            for (int i = tid; i < TSAMP * KC4; i += 256) {
                int ts = i >> 8;          // /KC4
                int cc = i & (KC4 - 1);
                int bb = s_b[ts];
                float4 v = make_float4(0.f, 0.f, 0.f, 0.f);
                if (bb >= 0)
                    v = gatt4[(size_t)bb * (CDIM / 4) + ct * KC4 + cc];
                s_att[ts][cc] = v;
            }
            __syncthreads();

            #pragma unroll
            for (int it = 0; it < KC4 / 32; ++it) {     // 8 iterations
                const int cc = it * 32 + lane;
                float4 w[4];
                #pragma unroll
                for (int ta = 0; ta < 4; ++ta)
                    w[ta] = W4[wrow[ta] + (size_t)ct * KC4 + cc];
                #pragma unroll
                for (int ts = 0; ts < TSAMP; ++ts) {
                    float4 av = s_att[ts][cc];
                    #pragma unroll
                    for (int ta = 0; ta < 4; ++ta) {
                        acc[ta][ts] += w[ta].x * av.x;
                        acc[ta][ts] += w[ta].y * av.y;
                        acc[ta][ts] += w[ta].z * av.z;
                        acc[ta][ts] += w[ta].w * av.w;
                    }
                }
            }
        }

        // butterfly reduce: every lane ends with full sums
        #pragma unroll
        for (int ta = 0; ta < 4; ++ta)
            #pragma unroll
            for (int ts = 0; ts < TSAMP; ++ts)
                #pragma unroll
                for (int off = 16; off > 0; off >>= 1)
                    acc[ta][ts] += __shfl_xor_sync(0xffffffffu, acc[ta][ts], off);

        // lane l stores pair (ta = l/8, ts = l%8)
        {
            int ta = lane >> 3;
            int ts = lane & 7;
            int a  = aw + ta;
            int bb = s_b[ts];
            if (a < NANS && bb >= 0)
                out[(size_t)bb * NANS + a] = acc[ta][ts] + bias[(size_t)d * NANS + a];
        }
        __syncthreads();   // protect s_b / s_att before next chunk rewrites
    }
}

// ---------------------------------------------------------------------------
extern "C" void kernel_launch(void* const* d_in, const int* in_sizes, int n_in,
                              void* d_out, int out_size) {
    const float* mask = (const float*)d_in[0];   // [B,1,14,14]
    const float* feat = (const float*)d_in[1];   // [B,C,14,14]
    const int*   inst = (const int*)d_in[2];     // [B] int64 or int32
    const float* Wm   = (const float*)d_in[3];   // [32,1845,2048]
    const float* bias = (const float*)d_in[4];   // [32,1845]
    float* out = (float*)d_out;                  // [B,1845]

    attend_kernel<<<dim3(32, 128), 256>>>(mask, feat);
    gemm_kernel<<<dim3((NANS + 31) / 32, NDESC), 256>>>(inst, Wm, bias, out);
}

// round 3
// speedup vs baseline: 1.6692x; 1.2080x over previous
#include <cuda_runtime.h>
#include <cuda_bf16.h>
#include <cstdint>

// Problem constants
#define BSZ   128
#define CDIM  2048
#define HW    196          // 14*14
#define NDESC 32
#define NANS  1845
#define CD4   (CDIM / 4)   // 512 float4 per attended row

// Scratch (no allocations allowed)
__device__ float g_att[BSZ * CDIM];      // attended [B, C]
__device__ int   g_cnt[NDESC];           // samples per descriptor
__device__ int   g_list[NDESC * BSZ];    // sample ids per descriptor

// ---------------------------------------------------------------------------
// Kernel A: attended[b,c] = (1/196) * sum_hw mask[b,hw] * feat[b,c,hw]
// grid (32, 128), block 256. Block (0,0) additionally computes the
// descriptor grouping tables (g_cnt / g_list) used by the GEMM.
// ---------------------------------------------------------------------------
__global__ void __launch_bounds__(256)
attend_kernel(const float* __restrict__ mask,
              const float* __restrict__ feat,
              const int* __restrict__ inst32) {
    __shared__ float4 smask[49];
    const int b   = blockIdx.y;
    const int tid = threadIdx.x;

    const float4* mrow = reinterpret_cast<const float4*>(mask + (size_t)b * HW);
    if (tid < 49) smask[tid] = mrow[tid];
    __syncthreads();

    const int warp = tid >> 5;
    const int lane = tid & 31;

    #pragma unroll
    for (int it = 0; it < 4; ++it) {
        const int c0 = blockIdx.x * 64 + it * 16 + warp * 2;
        const float4* fr0 =
            reinterpret_cast<const float4*>(feat + ((size_t)b * CDIM + c0) * HW);
        const float4* fr1 =
            reinterpret_cast<const float4*>(feat + ((size_t)b * CDIM + c0 + 1) * HW);

        float4 f0a = fr0[lane];
        float4 f1a = fr1[lane];
        float4 f0b, f1b;
        if (lane < 17) { f0b = fr0[lane + 32]; f1b = fr1[lane + 32]; }

        float4 ma = smask[lane];
        float s0 = f0a.x * ma.x + f0a.y * ma.y + f0a.z * ma.z + f0a.w * ma.w;
        float s1 = f1a.x * ma.x + f1a.y * ma.y + f1a.z * ma.z + f1a.w * ma.w;
        if (lane < 17) {
            float4 mb = smask[lane + 32];
            s0 += f0b.x * mb.x + f0b.y * mb.y + f0b.z * mb.z + f0b.w * mb.w;
            s1 += f1b.x * mb.x + f1b.y * mb.y + f1b.z * mb.z + f1b.w * mb.w;
        }
        #pragma unroll
        for (int off = 16; off > 0; off >>= 1) {
            s0 += __shfl_xor_sync(0xffffffffu, s0, off);
            s1 += __shfl_xor_sync(0xffffffffu, s1, off);
        }
        if (lane == 0) {
            g_att[(size_t)b * CDIM + c0]     = s0 * (1.0f / (float)HW);
            g_att[(size_t)b * CDIM + c0 + 1] = s1 * (1.0f / (float)HW);
        }
    }

    // ---- grouping tables, computed once by block (0,0) ----
    if (blockIdx.x == 0 && blockIdx.y == 0) {
        __shared__ int sh_inst[BSZ];
        __shared__ int sh_flag;
        if (tid == 0) sh_flag = 0;
        __syncthreads();
        if (tid < 64) {
            // int64 little-endian => odd 32-bit words of first 64 entries are 0
            if (inst32[2 * tid + 1] != 0) atomicOr(&sh_flag, 1);
        }
        __syncthreads();
        const bool is64 = (sh_flag == 0);
        if (tid < BSZ) sh_inst[tid] = is64 ? inst32[2 * tid] : inst32[tid];
        __syncthreads();
        if (tid == 0) {
            int cnt[NDESC];
            #pragma unroll
            for (int dd = 0; dd < NDESC; ++dd) cnt[dd] = 0;
            for (int bb = 0; bb < BSZ; ++bb) {
                int dd = sh_inst[bb];
                g_list[dd * BSZ + cnt[dd]++] = bb;
            }
            #pragma unroll
            for (int dd = 0; dd < NDESC; ++dd) g_cnt[dd] = cnt[dd];
        }
    }
}

// ---------------------------------------------------------------------------
// Kernel B: grouped GEMM.  preds[s,a] = sum_c att[s,c] * W[d,a,c] + bias[d,a]
// grid (58, 32). block 256 = 8 warps. Warp tile: 4 answers x 4 samples.
// Full-K attended tile (4 x 2048 f32 = 32 KB) staged once per sample chunk.
// W streamed with 8 independent LDG.128 in flight per warp (2-iter batches).
// ---------------------------------------------------------------------------
#define TSAMP 4

__global__ void __launch_bounds__(256, 3)
gemm_kernel(const float* __restrict__ Wm,
            const float* __restrict__ bias,
            float* __restrict__ out) {
    const int d     = blockIdx.y;
    const int count = g_cnt[d];
    if (count == 0) return;

    const int tid  = threadIdx.x;
    const int warp = tid >> 5;
    const int lane = tid & 31;

    __shared__ float4 s_att[TSAMP][CD4];   // 32 KB
    __shared__ int    s_b[TSAMP];

    const int aw = blockIdx.x * 32 + warp * 4;   // first of 4 answers
    const float4* __restrict__ W4 = reinterpret_cast<const float4*>(Wm);
    size_t wrow[4];
    #pragma unroll
    for (int ta = 0; ta < 4; ++ta) {
        int a = aw + ta; if (a >= NANS) a = NANS - 1;   // clamp; stores guarded
        wrow[ta] = ((size_t)d * NANS + a) * CD4;
    }
    const float4* __restrict__ gatt4 = reinterpret_cast<const float4*>(g_att);

    const int nchunks = (count + TSAMP - 1) / TSAMP;

    for (int sc = 0; sc < nchunks; ++sc) {
        if (tid < TSAMP) {
            int si = sc * TSAMP + tid;
            s_b[tid] = (si < count) ? g_list[d * BSZ + si] : -1;
        }
        __syncthreads();
        // stage attended tile (full K), zeros for padding samples
        for (int i = tid; i < TSAMP * CD4; i += 256) {
            int ts = i >> 9;            // / CD4
            int cc = i & (CD4 - 1);
            int bb = s_b[ts];
            float4 v = make_float4(0.f, 0.f, 0.f, 0.f);
            if (bb >= 0) v = gatt4[(size_t)bb * CD4 + cc];
            s_att[ts][cc] = v;
        }
        __syncthreads();

        float acc[4][TSAMP];
        #pragma unroll
        for (int ta = 0; ta < 4; ++ta)
            #pragma unroll
            for (int ts = 0; ts < TSAMP; ++ts) acc[ta][ts] = 0.0f;

        // K loop: 512 float4 / 32 lanes = 16 iters, batched by 2
        #pragma unroll
        for (int it = 0; it < CD4 / 32; it += 2) {
            const int cc0 = it * 32 + lane;
            const int cc1 = cc0 + 32;
            float4 w[2][4];
            #pragma unroll
            for (int ta = 0; ta < 4; ++ta) w[0][ta] = W4[wrow[ta] + cc0];
            #pragma unroll
            for (int ta = 0; ta < 4; ++ta) w[1][ta] = W4[wrow[ta] + cc1];

            #pragma unroll
            for (int h = 0; h < 2; ++h) {
                const int cc = it * 32 + h * 32 + lane;
                #pragma unroll
                for (int ts = 0; ts < TSAMP; ++ts) {
                    float4 av = s_att[ts][cc];
                    #pragma unroll
                    for (int ta = 0; ta < 4; ++ta) {
                        acc[ta][ts] += w[h][ta].x * av.x;
                        acc[ta][ts] += w[h][ta].y * av.y;
                        acc[ta][ts] += w[h][ta].z * av.z;
                        acc[ta][ts] += w[h][ta].w * av.w;
                    }
                }
            }
        }

        // butterfly reduce: every lane ends with full sums
        #pragma unroll
        for (int ta = 0; ta < 4; ++ta)
            #pragma unroll
            for (int ts = 0; ts < TSAMP; ++ts)
                #pragma unroll
                for (int off = 16; off > 0; off >>= 1)
                    acc[ta][ts] += __shfl_xor_sync(0xffffffffu, acc[ta][ts], off);

        // lane l (<16) stores pair (ta = l/4, ts = l%4)
        if (lane < 16) {
            int ta = lane >> 2;
            int ts = lane & 3;
            int a  = aw + ta;
            int bb = s_b[ts];
            if (a < NANS && bb >= 0)
                out[(size_t)bb * NANS + a] = acc[ta][ts] + bias[(size_t)d * NANS + a];
        }
        __syncthreads();   // protect s_b / s_att before next chunk rewrites
    }
}

// ---------------------------------------------------------------------------
extern "C" void kernel_launch(void* const* d_in, const int* in_sizes, int n_in,
                              void* d_out, int out_size) {
    const float* mask = (const float*)d_in[0];   // [B,1,14,14]
    const float* feat = (const float*)d_in[1];   // [B,C,14,14]
    const int*   inst = (const int*)d_in[2];     // [B] int64 or int32
    const float* Wm   = (const float*)d_in[3];   // [32,1845,2048]
    const float* bias = (const float*)d_in[4];   // [32,1845]
    float* out = (float*)d_out;                  // [B,1845]

    attend_kernel<<<dim3(32, 128), 256>>>(mask, feat, inst);
    gemm_kernel<<<dim3((NANS + 31) / 32, NDESC), 256>>>(Wm, bias, out);
}